// round 3
// baseline (speedup 1.0000x reference)
#include <cuda_runtime.h>
#include <math.h>

#define T_LEN 512
#define B_SZ  64
#define D_SZ  1024
#define H_SZ  512
#define L_SZ  5

#define NCTA 128
#define NTHR 256

// ---------------- scratch (device globals: no allocation allowed) ----------------
__device__ float g_XHt[T_LEN * H_SZ * B_SZ];   // [t][j][b]  x@W_H + b_H
__device__ float g_XCt[T_LEN * H_SZ * B_SZ];   // [t][j][b]  x@W_C + b_C
__device__ float g_h[2][H_SZ * B_SZ];          // hidden double buffer, [j][b]
__device__ float g_part[2][4][H_SZ][B_SZ];     // K-split partials: [gate][kg][j][b]
__device__ unsigned g_cnt = 0;                 // monotonic arrival counter
__device__ unsigned g_gen = 0;                 // monotonic generation (release)

// packed fp32x2 FMA (sm_100+): d = a*b + c on two lanes
__device__ __forceinline__ unsigned long long fma2(
    unsigned long long a, unsigned long long b, unsigned long long c) {
    unsigned long long d;
    asm("fma.rn.f32x2 %0, %1, %2, %3;" : "=l"(d) : "l"(a), "l"(b), "l"(c));
    return d;
}
union UF2 { unsigned long long u; float2 f; };

// ---------------- grid-wide barrier (persistent kernel, 128 co-resident CTAs) ----
__device__ __forceinline__ void gbar() {
    __syncthreads();
    if (threadIdx.x == 0) {
        __threadfence();
        unsigned ticket = atomicAdd(&g_cnt, 1u);
        unsigned target = (ticket >> 7) + 1u;
        if ((ticket & (NCTA - 1)) == (NCTA - 1)) {
            atomicExch(&g_gen, target);
        } else {
            while ((int)(*(volatile unsigned*)&g_gen - target) < 0) { }
        }
        __threadfence();
    }
    __syncthreads();
}

// ---------------- precompute: XHt/XCt[t][j][b] = x[t,b,:]@W[:,j] + bias[j] -------
__global__ void __launch_bounds__(NTHR) proj_kernel(
    const float* __restrict__ x,
    const float* __restrict__ Ww,
    const float* __restrict__ Wb,
    const int gate)
{
    __shared__ float As[32][128];
    __shared__ float Bs[32][64];
    float* __restrict__ dst = gate ? g_XCt : g_XHt;

    const int tid = threadIdx.x;
    const int bm  = blockIdx.x * 128;
    const int bn  = blockIdx.y * 64;
    const int tm  = tid & 15;
    const int tn  = tid >> 4;

    float acc[8][4];
#pragma unroll
    for (int i = 0; i < 8; i++)
#pragma unroll
        for (int j = 0; j < 4; j++) acc[i][j] = 0.0f;

    for (int k0 = 0; k0 < D_SZ; k0 += 32) {
#pragma unroll
        for (int r = 0; r < 4; r++) {
            int lin = tid + r * 256;
            int m = lin >> 3, kq = lin & 7;
            float4 v = *(const float4*)(x + (size_t)(bm + m) * D_SZ + k0 + kq * 4);
            As[kq * 4 + 0][m] = v.x;
            As[kq * 4 + 1][m] = v.y;
            As[kq * 4 + 2][m] = v.z;
            As[kq * 4 + 3][m] = v.w;
        }
#pragma unroll
        for (int r = 0; r < 2; r++) {
            int lin = tid + r * 256;
            int kk = lin >> 4, jq = lin & 15;
            *(float4*)&Bs[kk][jq * 4] =
                *(const float4*)(Ww + (size_t)(k0 + kk) * H_SZ + bn + jq * 4);
        }
        __syncthreads();
#pragma unroll
        for (int k = 0; k < 32; k++) {
            float4 a0 = *(const float4*)&As[k][tm * 4];
            float4 a1 = *(const float4*)&As[k][64 + tm * 4];
            float4 bv = *(const float4*)&Bs[k][tn * 4];
            float av[8] = {a0.x, a0.y, a0.z, a0.w, a1.x, a1.y, a1.z, a1.w};
            float bw[4] = {bv.x, bv.y, bv.z, bv.w};
#pragma unroll
            for (int i = 0; i < 8; i++)
#pragma unroll
                for (int j = 0; j < 4; j++)
                    acc[i][j] = fmaf(av[i], bw[j], acc[i][j]);
        }
        __syncthreads();
    }

#pragma unroll
    for (int i = 0; i < 8; i++) {
        int m = bm + ((i < 4) ? (tm * 4 + i) : (64 + tm * 4 + i - 4));
        int t = m >> 6, b = m & 63;
#pragma unroll
        for (int j = 0; j < 4; j++) {
            int jj = bn + tn * 4 + j;
            dst[(size_t)t * (H_SZ * B_SZ) + (size_t)jj * B_SZ + b] = acc[i][j] + Wb[jj];
        }
    }
}

// ---------------- persistent sequential kernel: 2 passes x 512 t x 5 layers ------
// Phase A: 128 CTAs = 32 j-groups x 4 k-groups; CTA tile = 64b x 16j x 128k x 2 gates.
//   Thread = 4b x 2j x 1 gate: per-k inner = 2 LDS.128 + 4 FFMA2 (FMA2-pipe bound).
//   R weights pre-duplicated {r,r} in smem so FFMA2 needs no lane packing.
// Phase B: 1 element/thread: reduce 4 partials + bias (+X proj at l==0),
//   tanh / __expf sigmoid, highway combine, write next hidden (+ outputs).
__global__ void __launch_bounds__(NTHR, 1) rhn_seq_kernel(
    const float* __restrict__ RHw, const float* __restrict__ RHb,
    const float* __restrict__ RCw, const float* __restrict__ RCb,
    float* __restrict__ out)
{
    const int tid = threadIdx.x;
    const int cta = blockIdx.x;

    __shared__ __align__(16) float  hs[32][64];      // [k][b]
    __shared__ __align__(16) float4 rdH[32][8];      // [k][jp] = {r(j0),r(j0),r(j1),r(j1)}
    __shared__ __align__(16) float4 rdC[32][8];

    g_h[0][cta * NTHR + tid] = 0.0f;
    gbar();

    const int jp   = tid & 7;              // j pair: j = j0 + 2*jp + {0,1}
    const int gate = (tid >> 3) & 1;       // 0 = H, 1 = C
    const int byq  = tid >> 4;             // b quad: b = byq*4 .. +3
    const int jg   = cta & 31;
    const int kg   = cta >> 5;
    const int j0   = jg * 16;
    const int k0   = kg * 128;

    // staging indices for R: one (kk, jp) pair per thread, both gates
    const int kk_s = tid >> 3;             // 0..31
    const int jp_s = tid & 7;              // 0..7

    const int e  = cta * NTHR + tid;       // phase-B element
    const int eb = e & 63;
    const int ej = e >> 6;

    int p = 0;
    for (int pass = 0; pass < 2; pass++)
    for (int t = 0; t < T_LEN; t++)
    for (int l = 0; l < L_SZ; l++) {
        const float* __restrict__ Rh = RHw + (size_t)l * H_SZ * H_SZ;
        const float* __restrict__ Rc = RCw + (size_t)l * H_SZ * H_SZ;
        const float* __restrict__ hp = g_h[p];

        unsigned long long a0 = 0ull, a1 = 0ull, a2 = 0ull, a3 = 0ull;

        // prefetch chunk 0
        float4 ph0, ph1;
        float2 prh, prc;
        {
            const float4* h4 = (const float4*)(hp + k0 * 64);
            ph0 = h4[tid];
            ph1 = h4[tid + 256];
            prh = *(const float2*)(Rh + (size_t)(k0 + kk_s) * H_SZ + j0 + 2 * jp_s);
            prc = *(const float2*)(Rc + (size_t)(k0 + kk_s) * H_SZ + j0 + 2 * jp_s);
        }
#pragma unroll
        for (int c = 0; c < 4; c++) {
            __syncthreads();
            ((float4*)hs)[tid]       = ph0;
            ((float4*)hs)[tid + 256] = ph1;
            rdH[kk_s][jp_s] = make_float4(prh.x, prh.x, prh.y, prh.y);
            rdC[kk_s][jp_s] = make_float4(prc.x, prc.x, prc.y, prc.y);
            __syncthreads();
            if (c < 3) {
                int kb = k0 + (c + 1) * 32;
                const float4* h4 = (const float4*)(hp + kb * 64);
                ph0 = h4[tid];
                ph1 = h4[tid + 256];
                prh = *(const float2*)(Rh + (size_t)(kb + kk_s) * H_SZ + j0 + 2 * jp_s);
                prc = *(const float2*)(Rc + (size_t)(kb + kk_s) * H_SZ + j0 + 2 * jp_s);
            }
            const float4* __restrict__ rds = gate ? &rdC[0][0] : &rdH[0][0];
#pragma unroll
            for (int kk = 0; kk < 32; kk++) {
                const ulonglong2 hv = *(const ulonglong2*)&hs[kk][byq * 4];
                const ulonglong2 rv = *(const ulonglong2*)&rds[kk * 8 + jp];
                a0 = fma2(hv.x, rv.x, a0);   // j0, b0b1
                a1 = fma2(hv.y, rv.x, a1);   // j0, b2b3
                a2 = fma2(hv.x, rv.y, a2);   // j1, b0b1
                a3 = fma2(hv.y, rv.y, a3);   // j1, b2b3
            }
        }
        {
            UF2 u0, u1, u2, u3;
            u0.u = a0; u1.u = a1; u2.u = a2; u3.u = a3;
            int j = j0 + 2 * jp;
            *(float4*)&g_part[gate][kg][j][byq * 4] =
                make_float4(u0.f.x, u0.f.y, u1.f.x, u1.f.y);
            *(float4*)&g_part[gate][kg][j + 1][byq * 4] =
                make_float4(u2.f.x, u2.f.y, u3.f.x, u3.f.y);
        }
        gbar();

        // ---- phase B ----
        {
            float sH = g_part[0][0][ej][eb] + g_part[0][1][ej][eb]
                     + g_part[0][2][ej][eb] + g_part[0][3][ej][eb];
            float sC = g_part[1][0][ej][eb] + g_part[1][1][ej][eb]
                     + g_part[1][2][ej][eb] + g_part[1][3][ej][eb];
            sH += RHb[l * H_SZ + ej];
            sC += RCb[l * H_SZ + ej];
            if (l == 0) {
                sH += g_XHt[(size_t)t * (H_SZ * B_SZ) + e];
                sC += g_XCt[(size_t)t * (H_SZ * B_SZ) + e];
            }
            float hold = g_h[p][e];
            float hl = tanhf(sH);
            float tl = 1.0f / (1.0f + __expf(-sC));
            float hn = hl * tl + hold * (1.0f - tl);
            g_h[p ^ 1][e] = hn;
            if (l == L_SZ - 1) {
                size_t o = (size_t)t * (B_SZ * 2 * H_SZ) + (size_t)eb * (2 * H_SZ)
                         + (size_t)pass * H_SZ + ej;
                out[o] = hn;
                if (t == T_LEN - 1) {
                    out[(size_t)T_LEN * (B_SZ * 2 * H_SZ) + (size_t)eb * (2 * H_SZ)
                        + (size_t)pass * H_SZ + ej] = hn;
                }
            }
        }
        gbar();
        p ^= 1;
    }
}

extern "C" void kernel_launch(void* const* d_in, const int* in_sizes, int n_in,
                              void* d_out, int out_size)
{
    const float* x   = (const float*)d_in[0];
    const float* WHw = (const float*)d_in[1];
    const float* WHb = (const float*)d_in[2];
    const float* WCw = (const float*)d_in[3];
    const float* WCb = (const float*)d_in[4];
    const float* RHw = (const float*)d_in[5];
    const float* RHb = (const float*)d_in[6];
    const float* RCw = (const float*)d_in[7];
    const float* RCb = (const float*)d_in[8];
    float* out = (float*)d_out;

    dim3 pg(256, 8);
    proj_kernel<<<pg, NTHR>>>(x, WHw, WHb, 0);
    proj_kernel<<<pg, NTHR>>>(x, WCw, WCb, 1);
    rhn_seq_kernel<<<NCTA, NTHR>>>(RHw, RHb, RCw, RCb, out);
}